// round 15
// baseline (speedup 1.0000x reference)
#include <cuda_runtime.h>
#include <cuda_fp16.h>
#include <cstdint>

#define SEQ    2048
#define DMODEL 2048
#define NHEAD  8
#define HD     256
#define BATCH  2
#define BH     (BATCH*NHEAD)
#define ROWS   (BATCH*SEQ)          // 4096
#define NQKV   (DMODEL + 2*HD)      // 2560

typedef __half h16;

// ---------------- scratch (device globals; alloc-guard compliant) ----------------
__device__ __align__(256) h16 s_xh[(size_t)ROWS*DMODEL];
__device__ __align__(256) h16 s_wqkv[(size_t)NQKV*DMODEL];
__device__ __align__(256) h16 s_wo[(size_t)DMODEL*DMODEL];
__device__ __align__(256) h16 s_qh[(size_t)ROWS*DMODEL];
__device__ __align__(256) h16 s_kh[(size_t)ROWS*HD];
__device__ __align__(256) h16 s_vt[(size_t)BATCH*HD*SEQ];
__device__ __align__(256) h16 s_ph[(size_t)BH*SEQ*SEQ];
__device__ __align__(256) h16 s_ah[(size_t)ROWS*DMODEL];
__device__ __align__(16) float g_qkv[(size_t)ROWS*NQKV];    // [row][2560]: Q|K|V

// ---------------- helpers ----------------
__device__ __forceinline__ uint32_t smem_u32(const void* p) {
    uint32_t a;
    asm("{ .reg .u64 t; cvta.to.shared.u64 t, %1; cvt.u32.u64 %0, t; }" : "=r"(a) : "l"(p));
    return a;
}
#define SWZ(o) ((o) ^ (((o) >> 3) & 0x70))

__device__ __forceinline__ void cp16(uint32_t saddr, const void* gaddr) {
    asm volatile("cp.async.cg.shared.global [%0], [%1], 16;" :: "r"(saddr), "l"(gaddr));
}
__device__ __forceinline__ void cp_commit() { asm volatile("cp.async.commit_group;"); }
template<int N> __device__ __forceinline__ void cp_wait() {
    asm volatile("cp.async.wait_group %0;" :: "n"(N));
}
__device__ __forceinline__ void ldsm4(uint32_t* r, uint32_t addr) {
    asm volatile("ldmatrix.sync.aligned.m8n8.x4.shared.b16 {%0,%1,%2,%3}, [%4];"
                 : "=r"(r[0]), "=r"(r[1]), "=r"(r[2]), "=r"(r[3]) : "r"(addr));
}
__device__ __forceinline__ void mma16816(float* c, const uint32_t* a, const uint32_t* b) {
    asm volatile(
        "mma.sync.aligned.m16n8k16.row.col.f32.f16.f16.f32 "
        "{%0,%1,%2,%3}, {%4,%5,%6,%7}, {%8,%9}, {%0,%1,%2,%3};"
        : "+f"(c[0]), "+f"(c[1]), "+f"(c[2]), "+f"(c[3])
        : "r"(a[0]), "r"(a[1]), "r"(a[2]), "r"(a[3]), "r"(b[0]), "r"(b[1]));
}
__device__ __forceinline__ uint32_t pack2h(float x, float y) {
    return (uint32_t)__half_as_ushort(__float2half_rn(x)) |
           ((uint32_t)__half_as_ushort(__float2half_rn(y)) << 16);
}

#define BK 64
extern __shared__ char dynsmem[];

// =========== BM=64 GEMM: C[64,128] tile = alpha * A[64,K] @ B[128,K]^T (both fp16) ==
#define G64_A 0
#define G64_B 8192
#define G64_STRIDE 24576
#define SMEM64_BYTES (2*G64_STRIDE)   // 49152

__device__ __forceinline__ void load_stage64(
    uint32_t st, int tid, int k0, int rowBase, int colBase,
    const h16* A, int lda, const h16* B, int ldb)
{
#pragma unroll
    for (int i = 0; i < 2; i++) {
        int idx = tid + i * 256;
        int r = idx >> 3, ch = idx & 7;
        uint32_t so = SWZ((uint32_t)(r * 128 + ch * 16));
        cp16(st + G64_A + so, A + (size_t)(rowBase + r) * lda + k0 + ch * 8);
    }
#pragma unroll
    for (int i = 0; i < 4; i++) {
        int idx = tid + i * 256;
        int r = idx >> 3, ch = idx & 7;
        uint32_t so = SWZ((uint32_t)(r * 128 + ch * 16));
        cp16(st + G64_B + so, B + (size_t)(colBase + r) * ldb + k0 + ch * 8);
    }
}

// EPI 0: fp32 out (alpha).  EPI 1: fp16 rounded out.
template<int EPI>
__device__ void hmma_gemm64(const h16* __restrict__ A, int lda,
                            const h16* __restrict__ B, int ldb,
                            float* __restrict__ C, h16* __restrict__ Ch,
                            int ldc, int K, float alpha, int rowBlk, int colBlk)
{
    const uint32_t sb = smem_u32(dynsmem);
    const int tid = threadIdx.x;
    const int lane = tid & 31, wid = tid >> 5;
    const int warpM = wid >> 2, warpN = wid & 3;    // 2 x 4
    const int rowBase = rowBlk * 64, colBase = colBlk * 128;

    float acc[2][4][4];
#pragma unroll
    for (int mf = 0; mf < 2; mf++)
#pragma unroll
        for (int nf = 0; nf < 4; nf++)
#pragma unroll
            for (int c = 0; c < 4; c++) acc[mf][nf][c] = 0.f;

    const int KI = K / BK;
    load_stage64(sb, tid, 0, rowBase, colBase, A, lda, B, ldb);
    cp_commit();
    load_stage64(sb + G64_STRIDE, tid, BK, rowBase, colBase, A, lda, B, ldb);
    cp_commit();

    for (int it = 0; it < KI; it++) {
        cp_wait<1>();
        __syncthreads();
        const uint32_t st = sb + (it & 1) * G64_STRIDE;
#pragma unroll
        for (int ks = 0; ks < 4; ks++) {
            uint32_t ah[2][4], bf[4][2];
            const int kk = ks * 16 + (lane >> 4) * 8;
#pragma unroll
            for (int mf = 0; mf < 2; mf++) {
                int row = warpM * 32 + mf * 16 + (lane & 15);
                ldsm4(ah[mf], st + G64_A + SWZ((uint32_t)(row * 128 + kk * 2)));
            }
#pragma unroll
            for (int nb = 0; nb < 2; nb++) {
                int nrow = warpN * 32 + nb * 16 + (lane & 15);
                uint32_t t[4];
                ldsm4(t, st + G64_B + SWZ((uint32_t)(nrow * 128 + kk * 2)));
                bf[nb*2][0] = t[0]; bf[nb*2][1] = t[2];
                bf[nb*2+1][0] = t[1]; bf[nb*2+1][1] = t[3];
            }
#pragma unroll
            for (int mf = 0; mf < 2; mf++)
#pragma unroll
                for (int nf = 0; nf < 4; nf++) mma16816(acc[mf][nf], ah[mf], bf[nf]);
        }
        __syncthreads();
        if (it + 2 < KI)
            load_stage64(sb + (it & 1) * G64_STRIDE, tid, (it + 2) * BK,
                         rowBase, colBase, A, lda, B, ldb);
        cp_commit();
    }
    cp_wait<0>();

#pragma unroll
    for (int mf = 0; mf < 2; mf++) {
        int row0 = rowBase + warpM * 32 + mf * 16 + (lane >> 2);
#pragma unroll
        for (int nf = 0; nf < 4; nf++) {
            int col = colBase + warpN * 32 + nf * 8 + (lane & 3) * 2;
            if (EPI == 0) {
                float2 v0 = {alpha * acc[mf][nf][0], alpha * acc[mf][nf][1]};
                float2 v1 = {alpha * acc[mf][nf][2], alpha * acc[mf][nf][3]};
                *(float2*)(C + (size_t)row0 * ldc + col) = v0;
                *(float2*)(C + (size_t)(row0 + 8) * ldc + col) = v1;
            } else {
                *(uint32_t*)(Ch + (size_t)row0 * ldc + col) =
                    pack2h(acc[mf][nf][0], acc[mf][nf][1]);
                *(uint32_t*)(Ch + (size_t)(row0 + 8) * ldc + col) =
                    pack2h(acc[mf][nf][2], acc[mf][nf][3]);
            }
        }
    }
}

// =========== BM=128 single-product GEMM (scores): fp32 out, 3-stage pipeline ========
#define S1_A 0
#define S1_B 16384
#define S1_STRIDE 32768
#define S1_STAGES 3
#define SMEM1_BYTES (S1_STAGES*S1_STRIDE)   // 98304

__device__ __forceinline__ void load_stage1(
    uint32_t st, int tid, int k0, int rowBase, int colBase,
    const h16* A, int lda, const h16* B, int ldb)
{
#pragma unroll
    for (int i = 0; i < 4; i++) {
        int idx = tid + i * 256;
        int r = idx >> 3, ch = idx & 7;
        uint32_t so = SWZ((uint32_t)(r * 128 + ch * 16));
        cp16(st + S1_A + so, A + (size_t)(rowBase + r) * lda + k0 + ch * 8);
        cp16(st + S1_B + so, B + (size_t)(colBase + r) * ldb + k0 + ch * 8);
    }
}

__device__ void hmma_gemm128(const h16* __restrict__ A, int lda,
                             const h16* __restrict__ B, int ldb,
                             float* __restrict__ C, int ldc, int K, float alpha,
                             int rowBlk, int colBlk)
{
    const uint32_t sb = smem_u32(dynsmem);
    const int tid = threadIdx.x;
    const int lane = tid & 31, wid = tid >> 5;
    const int warpM = wid >> 2, warpN = wid & 3;
    const int rowBase = rowBlk * 128, colBase = colBlk * 128;

    float acc[4][4][4];
#pragma unroll
    for (int mf = 0; mf < 4; mf++)
#pragma unroll
        for (int nf = 0; nf < 4; nf++)
#pragma unroll
            for (int c = 0; c < 4; c++) acc[mf][nf][c] = 0.f;

    const int KI = K / BK;     // = 4 for scores
#pragma unroll
    for (int s = 0; s < S1_STAGES; s++) {
        if (s < KI) load_stage1(sb + s * S1_STRIDE, tid, s * BK, rowBase, colBase, A, lda, B, ldb);
        cp_commit();
    }

    int stage = 0;
    for (int it = 0; it < KI; it++) {
        cp_wait<S1_STAGES - 1>();
        __syncthreads();
        const uint32_t st = sb + stage * S1_STRIDE;
#pragma unroll
        for (int ks = 0; ks < 4; ks++) {
            uint32_t ah[4][4], bf[4][2];
            const int kk = ks * 16 + (lane >> 4) * 8;
#pragma unroll
            for (int mf = 0; mf < 4; mf++) {
                int row = warpM * 64 + mf * 16 + (lane & 15);
                ldsm4(ah[mf], st + S1_A + SWZ((uint32_t)(row * 128 + kk * 2)));
            }
#pragma unroll
            for (int nb = 0; nb < 2; nb++) {
                int nrow = warpN * 32 + nb * 16 + (lane & 15);
                uint32_t t[4];
                ldsm4(t, st + S1_B + SWZ((uint32_t)(nrow * 128 + kk * 2)));
                bf[nb*2][0] = t[0]; bf[nb*2][1] = t[2];
                bf[nb*2+1][0] = t[1]; bf[nb*2+1][1] = t[3];
            }
#pragma unroll
            for (int mf = 0; mf < 4; mf++)
#pragma unroll
                for (int nf = 0; nf < 4; nf++) mma16816(acc[mf][nf], ah[mf], bf[nf]);
        }
        __syncthreads();
        if (it + S1_STAGES < KI)
            load_stage1(sb + stage * S1_STRIDE, tid, (it + S1_STAGES) * BK,
                        rowBase, colBase, A, lda, B, ldb);
        cp_commit();
        stage = (stage + 1 == S1_STAGES) ? 0 : stage + 1;
    }
    cp_wait<0>();

#pragma unroll
    for (int mf = 0; mf < 4; mf++) {
        int row0 = rowBase + warpM * 64 + mf * 16 + (lane >> 2);
#pragma unroll
        for (int nf = 0; nf < 4; nf++) {
            int col = colBase + warpN * 32 + nf * 8 + (lane & 3) * 2;
            float2 v0 = {alpha * acc[mf][nf][0], alpha * acc[mf][nf][1]};
            float2 v1 = {alpha * acc[mf][nf][2], alpha * acc[mf][nf][3]};
            *(float2*)(C + (size_t)row0 * ldc + col) = v0;
            *(float2*)(C + (size_t)(row0 + 8) * ldc + col) = v1;
        }
    }
}

// ---------------- GEMM wrappers ----------------
__global__ __launch_bounds__(256) void k_gemm_f32out64(
    const h16* A, int lda, const h16* B, int ldb, float* C, int ldc, int K, float alpha)
{
    hmma_gemm64<0>(A, lda, B, ldb, C, nullptr, ldc, K, alpha, blockIdx.y, blockIdx.x);
}

// scores grid: 256 tiles/head. t in [0,120): upper-tri ZERO tiles (write 0, retire fast,
// stores drain under following MMA tiles). t in [120,256): work tiles, triangular decode.
__global__ __launch_bounds__(256, 2) void k_gemm_scores(
    const h16* qh, const h16* kh, float* W)
{
    const int bh = blockIdx.z, b = bh / NHEAD, h = bh % NHEAD;
    float* W0 = W + (size_t)bh * SEQ * SEQ;
    const int t = blockIdx.x;

    if (t < 120) {
        // zero tile: decode z -> (tx, ty) with tx > ty; tx in 1..15
        int a = (int)((sqrtf(8.0f * t + 1.0f) + 1.0f) * 0.5f);
        while (a * (a - 1) / 2 > t) a--;
        while ((a + 1) * a / 2 <= t) a++;
        const int tx = a, ty = t - a * (a - 1) / 2;
        const int rowBase = ty * 128, colBase = tx * 128;
        const float4 z = {0.f, 0.f, 0.f, 0.f};
        const int tid = threadIdx.x;
#pragma unroll
        for (int i = 0; i < 16; i++) {
            int lin = tid + i * 256;              // float4 units, 32 per row
            int r = lin >> 5, c = (lin & 31) * 4;
            *(float4*)(W0 + (size_t)(rowBase + r) * SEQ + colBase + c) = z;
        }
        return;
    }

    const int tw = t - 120;                       // 0..135 work tiles
    int ty = (int)((sqrtf(8.0f * tw + 1.0f) - 1.0f) * 0.5f);
    while ((ty + 1) * (ty + 2) / 2 <= tw) ty++;
    while (ty * (ty + 1) / 2 > tw) ty--;
    const int tx = tw - ty * (ty + 1) / 2;

    size_t qa = (size_t)b * SEQ * DMODEL + (size_t)h * HD;
    size_t ka = (size_t)b * SEQ * HD;
    hmma_gemm128(qh + qa, DMODEL, kh + ka, HD, W0, SEQ, HD, 0.0625f, ty, tx);
}

// PV: BM=64 rows, LPT order (largest-K first), 64-granular causal clamp
__global__ __launch_bounds__(256) void k_gemm_pv(
    const h16* ph, const h16* vt, h16* ah_out)
{
    const int bh = blockIdx.z, b = bh / NHEAD, h = bh % NHEAD;
    const int yy = gridDim.y - 1 - blockIdx.y;
    size_t pa = (size_t)bh * SEQ * SEQ;
    size_t va = (size_t)b * HD * SEQ;
    int kmax = (yy + 1) * 64;
    size_t co = (size_t)b * SEQ * DMODEL + (size_t)h * HD;
    hmma_gemm64<1>(ph + pa, SEQ, vt + va, SEQ, nullptr, ah_out + co, DMODEL, kmax, 1.0f,
                   yy, blockIdx.x);
}

// ---------------- fused fp32 -> fp16 rounding over all 5 segments ----------------
#define CVT_N0 (ROWS*DMODEL/4)
#define CVT_N1 (DMODEL*DMODEL/4)
#define CVT_N2 (DMODEL*DMODEL/4)
#define CVT_N3 (HD*DMODEL/4)
#define CVT_N4 (HD*DMODEL/4)
#define CVT_TOTAL (CVT_N0+CVT_N1+CVT_N2+CVT_N3+CVT_N4)

__global__ __launch_bounds__(256) void k_cvt_all(
    const float4* __restrict__ X, const float4* __restrict__ Wq,
    const float4* __restrict__ Wo, const float4* __restrict__ Wk,
    const float4* __restrict__ Wv,
    uint2* __restrict__ xh, uint2* __restrict__ wqkv, uint2* __restrict__ wo)
{
    int i = blockIdx.x * 256 + threadIdx.x;
    if (i >= CVT_TOTAL) return;
    const float4* src;
    uint2* dst;
    int j = i;
    if (j < CVT_N0) { src = X; dst = xh; }
    else if ((j -= CVT_N0) < CVT_N1) { src = Wq; dst = wqkv; }
    else if ((j -= CVT_N1) < CVT_N2) { src = Wo; dst = wo; }
    else if ((j -= CVT_N2) < CVT_N3) { src = Wk; dst = wqkv + (size_t)DMODEL * DMODEL / 4; }
    else { j -= CVT_N3; src = Wv; dst = wqkv + (size_t)(DMODEL + HD) * DMODEL / 4; }
    float4 v = src[j];
    uint2 O;
    O.x = pack2h(v.x, v.y);
    O.y = pack2h(v.z, v.w);
    dst[j] = O;
}

// ---------------- fused RoPE + V-transpose (Q/K single fp16) ----------------
#define VT_BLOCKS ((SEQ/32)*(HD/32)*BATCH)           // 1024
#define ROPE_TOTAL (ROWS*(NHEAD+1)*128)
#define ROPE_BLOCKS ((ROPE_TOTAL+255)/256)

__global__ __launch_bounds__(256) void k_rope_vt(const int* __restrict__ pos) {
    const int bid = blockIdx.x;
    const int tid = threadIdx.x;
    if (bid < VT_BLOCKS) {
        __shared__ float t[32][33];
        int b = bid >> 9;
        int rem = bid & 511;
        int kblk = rem & 63;
        int nblk = rem >> 6;
        int k0 = kblk * 32, n0 = nblk * 32;
        int tx = tid & 31, ty = tid >> 5;
#pragma unroll
        for (int i = 0; i < 32; i += 8)
            t[ty + i][tx] = g_qkv[((size_t)(b * SEQ + k0 + ty + i)) * NQKV + DMODEL + HD + n0 + tx];
        __syncthreads();
#pragma unroll
        for (int i = 0; i < 32; i += 8) {
            float v = t[tx][ty + i];
            size_t o = ((size_t)(b * HD + n0 + ty + i)) * SEQ + k0 + tx;
            s_vt[o] = __float2half_rn(v);
        }
        return;
    }
    int idx = (bid - VT_BLOCKS) * 256 + tid;
    if (idx >= ROPE_TOTAL) return;
    int j = idx & 127;
    int rest = idx >> 7;
    int slot = rest % (NHEAD + 1);
    int row = rest / (NHEAD + 1);
    float p = (float)pos[row];
    float f = exp2f(-((float)(2 * j) * (1.0f / (float)HD)) * 13.287712379549449f);
    float sv, cv;
    sincosf(p * f, &sv, &cv);
    size_t src = (slot < NHEAD) ? ((size_t)row * NQKV + slot * HD + j)
                                : ((size_t)row * NQKV + DMODEL + j);
    float x1 = g_qkv[src], x2 = g_qkv[src + 128];
    float y1 = x1 * cv - x2 * sv;
    float y2 = x2 * cv + x1 * sv;
    if (slot < NHEAD) {
        size_t o = (size_t)row * DMODEL + slot * HD + j;
        s_qh[o] = __float2half_rn(y1);
        s_qh[o + 128] = __float2half_rn(y2);
    } else {
        size_t o = (size_t)row * HD + j;
        s_kh[o] = __float2half_rn(y1);
        s_kh[o + 128] = __float2half_rn(y2);
    }
}

// ---------------- softmax v4: bounded stores (fp32 to 128-boundary, fp16 to 64) -----
__global__ __launch_bounds__(256) void k_softmax(float* __restrict__ w) {
    const int row = blockIdx.x;               // bh*SEQ + q
    const int q = row & (SEQ - 1);
    const int tid = threadIdx.x;
    float4* p4 = (float4*)(w + (size_t)row * SEQ);
    uint2* ph2 = (uint2*)(s_ph + (size_t)row * SEQ);

    const float NEG = -3.4e38f;
    const int c0 = tid * 4, c1 = (tid + 256) * 4;
    float4 v0 = (c0 <= q) ? p4[tid]       : make_float4(NEG, NEG, NEG, NEG);
    float4 v1 = (c1 <= q) ? p4[tid + 256] : make_float4(NEG, NEG, NEG, NEG);
    float x[8] = {v0.x, v0.y, v0.z, v0.w, v1.x, v1.y, v1.z, v1.w};
#pragma unroll
    for (int j = 0; j < 4; j++) if (c0 + j > q) x[j] = NEG;
#pragma unroll
    for (int j = 0; j < 4; j++) if (c1 + j > q) x[4 + j] = NEG;

    float m = NEG;
#pragma unroll
    for (int j = 0; j < 8; j++) m = fmaxf(m, x[j]);
#pragma unroll
    for (int o = 16; o > 0; o >>= 1) m = fmaxf(m, __shfl_xor_sync(0xFFFFFFFFu, m, o));

    __shared__ float red[8];
    __shared__ float bc[2];
    if ((tid & 31) == 0) red[tid >> 5] = m;
    __syncthreads();
    if (tid < 32) {
        float t = (tid < 8) ? red[tid] : NEG;
#pragma unroll
        for (int o = 4; o > 0; o >>= 1) t = fmaxf(t, __shfl_xor_sync(0xFFFFFFFFu, t, o));
        if (tid == 0) bc[0] = t;
    }
    __syncthreads();
    m = bc[0];

    float e[8];
    float s = 0.f;
#pragma unroll
    for (int j = 0; j < 8; j++) {
        e[j] = (x[j] > -1e37f) ? expf(x[j] - m) : 0.f;
        s += e[j];
    }
#pragma unroll
    for (int o = 16; o > 0; o >>= 1) s += __shfl_xor_sync(0xFFFFFFFFu, s, o);
    if ((tid & 31) == 0) red[tid >> 5] = s;
    __syncthreads();
    if (tid < 32) {
        float t = (tid < 8) ? red[tid] : 0.f;
#pragma unroll
        for (int o = 4; o > 0; o >>= 1) t += __shfl_xor_sync(0xFFFFFFFFu, t, o);
        if (tid == 0) bc[1] = t;
    }
    __syncthreads();
    const float inv = 1.0f / bc[1];

#pragma unroll
    for (int j = 0; j < 8; j++) e[j] *= inv;
    const int kmax128 = ((q >> 7) + 1) << 7;   // fp32 zeros beyond this written by scores tiles
    const int kmax64  = ((q >> 6) + 1) << 6;   // PV never reads P beyond this
    float4 o0 = {e[0], e[1], e[2], e[3]};
    float4 o1 = {e[4], e[5], e[6], e[7]};
    if (c0 < kmax128) p4[tid] = o0;
    if (c1 < kmax128) p4[tid + 256] = o1;
    uint2 h0 = {pack2h(e[0], e[1]), pack2h(e[2], e[3])};
    uint2 h1 = {pack2h(e[4], e[5]), pack2h(e[6], e[7])};
    if (c0 < kmax64) ph2[tid] = h0;
    if (c1 < kmax64) ph2[tid + 256] = h1;
}

// ---------------- launch ----------------
static void* sym(const void* s) { void* p = nullptr; cudaGetSymbolAddress(&p, s); return p; }

extern "C" void kernel_launch(void* const* d_in, const int* in_sizes, int n_in,
                              void* d_out, int out_size) {
    const float* hidden = (const float*)d_in[0];
    const int*   pos    = (const int*)d_in[2];
    const float* Wq     = (const float*)d_in[3];
    const float* Wk     = (const float*)d_in[4];
    const float* Wv     = (const float*)d_in[5];
    const float* Wo     = (const float*)d_in[6];

    float* out      = (float*)d_out;
    float* weights  = out + (size_t)ROWS * DMODEL;   // (B, H, S, S)

    cudaFuncSetAttribute(k_gemm_f32out64, cudaFuncAttributeMaxDynamicSharedMemorySize, SMEM64_BYTES);
    cudaFuncSetAttribute(k_gemm_pv,       cudaFuncAttributeMaxDynamicSharedMemorySize, SMEM64_BYTES);
    cudaFuncSetAttribute(k_gemm_scores,   cudaFuncAttributeMaxDynamicSharedMemorySize, SMEM1_BYTES);

    h16 *xh = (h16*)sym(s_xh), *wqkv = (h16*)sym(s_wqkv), *wo = (h16*)sym(s_wo);
    h16 *qh = (h16*)sym(s_qh), *kh = (h16*)sym(s_kh), *vt = (h16*)sym(s_vt);
    h16 *ph = (h16*)sym(s_ph), *ah = (h16*)sym(s_ah);
    float *gqkv = (float*)sym(g_qkv);

    // 1. one fused rounding pass over X, Wq, Wo, Wk, Wv
    k_cvt_all<<<(CVT_TOTAL + 255) / 256, 256>>>(
        (const float4*)hidden, (const float4*)Wq, (const float4*)Wo,
        (const float4*)Wk, (const float4*)Wv,
        (uint2*)xh, (uint2*)wqkv, (uint2*)wo);

    // 2. fused QKV projection (BM=64 tiles: 1280 CTAs)
    k_gemm_f32out64<<<dim3(NQKV / 128, ROWS / 64), 256, SMEM64_BYTES>>>(
        xh, DMODEL, wqkv, DMODEL, gqkv, NQKV, DMODEL, 1.0f);

    // 3. fused RoPE + V transpose (Q, K single fp16)
    k_rope_vt<<<VT_BLOCKS + ROPE_BLOCKS, 256>>>(pos);

    // 4. scores: 120 zero tiles (front) + 136 work tiles per head
    k_gemm_scores<<<dim3(256, 1, BH), 256, SMEM1_BYTES>>>(qh, kh, weights);

    // 5. softmax v4 (bounded stores)
    k_softmax<<<BH * SEQ, 256>>>(weights);

    // 6. P @ V (BM=64, 64-granular causal clamp, LPT) -> fp16 attn
    k_gemm_pv<<<dim3(HD / 128, SEQ / 64, BH), 256, SMEM64_BYTES>>>(ph, vt, ah);

    // 7. output projection (BM=64 tiles: 1024 CTAs)
    k_gemm_f32out64<<<dim3(DMODEL / 128, ROWS / 64), 256, SMEM64_BYTES>>>(
        ah, DMODEL, wo, DMODEL, out, DMODEL, DMODEL, 1.0f);
}

// round 16
// speedup vs baseline: 1.0154x; 1.0154x over previous
#include <cuda_runtime.h>
#include <cuda_fp16.h>
#include <cstdint>

#define SEQ    2048
#define DMODEL 2048
#define NHEAD  8
#define HD     256
#define BATCH  2
#define BH     (BATCH*NHEAD)
#define ROWS   (BATCH*SEQ)          // 4096
#define NQKV   (DMODEL + 2*HD)      // 2560

typedef __half h16;

// ---------------- scratch (device globals; alloc-guard compliant) ----------------
__device__ __align__(256) h16 s_xh[(size_t)ROWS*DMODEL];
__device__ __align__(256) h16 s_wqkv[(size_t)NQKV*DMODEL];
__device__ __align__(256) h16 s_wo[(size_t)DMODEL*DMODEL];
__device__ __align__(256) h16 s_qh[(size_t)ROWS*DMODEL];
__device__ __align__(256) h16 s_kh[(size_t)ROWS*HD];
__device__ __align__(256) h16 s_vt[(size_t)BATCH*HD*SEQ];
__device__ __align__(256) h16 s_ph[(size_t)BH*SEQ*SEQ];   // raw fp16 scores, then P in place
__device__ __align__(256) h16 s_ah[(size_t)ROWS*DMODEL];
__device__ __align__(16) float g_qkv[(size_t)ROWS*NQKV];    // [row][2560]: Q|K|V

// ---------------- helpers ----------------
__device__ __forceinline__ uint32_t smem_u32(const void* p) {
    uint32_t a;
    asm("{ .reg .u64 t; cvta.to.shared.u64 t, %1; cvt.u32.u64 %0, t; }" : "=r"(a) : "l"(p));
    return a;
}
#define SWZ(o) ((o) ^ (((o) >> 3) & 0x70))

__device__ __forceinline__ void cp16(uint32_t saddr, const void* gaddr) {
    asm volatile("cp.async.cg.shared.global [%0], [%1], 16;" :: "r"(saddr), "l"(gaddr));
}
__device__ __forceinline__ void cp_commit() { asm volatile("cp.async.commit_group;"); }
template<int N> __device__ __forceinline__ void cp_wait() {
    asm volatile("cp.async.wait_group %0;" :: "n"(N));
}
__device__ __forceinline__ void ldsm4(uint32_t* r, uint32_t addr) {
    asm volatile("ldmatrix.sync.aligned.m8n8.x4.shared.b16 {%0,%1,%2,%3}, [%4];"
                 : "=r"(r[0]), "=r"(r[1]), "=r"(r[2]), "=r"(r[3]) : "r"(addr));
}
__device__ __forceinline__ void mma16816(float* c, const uint32_t* a, const uint32_t* b) {
    asm volatile(
        "mma.sync.aligned.m16n8k16.row.col.f32.f16.f16.f32 "
        "{%0,%1,%2,%3}, {%4,%5,%6,%7}, {%8,%9}, {%0,%1,%2,%3};"
        : "+f"(c[0]), "+f"(c[1]), "+f"(c[2]), "+f"(c[3])
        : "r"(a[0]), "r"(a[1]), "r"(a[2]), "r"(a[3]), "r"(b[0]), "r"(b[1]));
}
__device__ __forceinline__ uint32_t pack2h(float x, float y) {
    return (uint32_t)__half_as_ushort(__float2half_rn(x)) |
           ((uint32_t)__half_as_ushort(__float2half_rn(y)) << 16);
}

#define BK 64
extern __shared__ char dynsmem[];

// =========== BM=64 GEMM: C[64,128] tile = alpha * A[64,K] @ B[128,K]^T (both fp16) ==
#define G64_A 0
#define G64_B 8192
#define G64_STRIDE 24576
#define SMEM64_BYTES (2*G64_STRIDE)   // 49152

__device__ __forceinline__ void load_stage64(
    uint32_t st, int tid, int k0, int rowBase, int colBase,
    const h16* A, int lda, const h16* B, int ldb)
{
#pragma unroll
    for (int i = 0; i < 2; i++) {
        int idx = tid + i * 256;
        int r = idx >> 3, ch = idx & 7;
        uint32_t so = SWZ((uint32_t)(r * 128 + ch * 16));
        cp16(st + G64_A + so, A + (size_t)(rowBase + r) * lda + k0 + ch * 8);
    }
#pragma unroll
    for (int i = 0; i < 4; i++) {
        int idx = tid + i * 256;
        int r = idx >> 3, ch = idx & 7;
        uint32_t so = SWZ((uint32_t)(r * 128 + ch * 16));
        cp16(st + G64_B + so, B + (size_t)(colBase + r) * ldb + k0 + ch * 8);
    }
}

// EPI 0: fp32 out (alpha).  EPI 1: fp16 rounded out.
template<int EPI>
__device__ void hmma_gemm64(const h16* __restrict__ A, int lda,
                            const h16* __restrict__ B, int ldb,
                            float* __restrict__ C, h16* __restrict__ Ch,
                            int ldc, int K, float alpha, int rowBlk, int colBlk)
{
    const uint32_t sb = smem_u32(dynsmem);
    const int tid = threadIdx.x;
    const int lane = tid & 31, wid = tid >> 5;
    const int warpM = wid >> 2, warpN = wid & 3;    // 2 x 4
    const int rowBase = rowBlk * 64, colBase = colBlk * 128;

    float acc[2][4][4];
#pragma unroll
    for (int mf = 0; mf < 2; mf++)
#pragma unroll
        for (int nf = 0; nf < 4; nf++)
#pragma unroll
            for (int c = 0; c < 4; c++) acc[mf][nf][c] = 0.f;

    const int KI = K / BK;
    load_stage64(sb, tid, 0, rowBase, colBase, A, lda, B, ldb);
    cp_commit();
    load_stage64(sb + G64_STRIDE, tid, BK, rowBase, colBase, A, lda, B, ldb);
    cp_commit();

    for (int it = 0; it < KI; it++) {
        cp_wait<1>();
        __syncthreads();
        const uint32_t st = sb + (it & 1) * G64_STRIDE;
#pragma unroll
        for (int ks = 0; ks < 4; ks++) {
            uint32_t ah[2][4], bf[4][2];
            const int kk = ks * 16 + (lane >> 4) * 8;
#pragma unroll
            for (int mf = 0; mf < 2; mf++) {
                int row = warpM * 32 + mf * 16 + (lane & 15);
                ldsm4(ah[mf], st + G64_A + SWZ((uint32_t)(row * 128 + kk * 2)));
            }
#pragma unroll
            for (int nb = 0; nb < 2; nb++) {
                int nrow = warpN * 32 + nb * 16 + (lane & 15);
                uint32_t t[4];
                ldsm4(t, st + G64_B + SWZ((uint32_t)(nrow * 128 + kk * 2)));
                bf[nb*2][0] = t[0]; bf[nb*2][1] = t[2];
                bf[nb*2+1][0] = t[1]; bf[nb*2+1][1] = t[3];
            }
#pragma unroll
            for (int mf = 0; mf < 2; mf++)
#pragma unroll
                for (int nf = 0; nf < 4; nf++) mma16816(acc[mf][nf], ah[mf], bf[nf]);
        }
        __syncthreads();
        if (it + 2 < KI)
            load_stage64(sb + (it & 1) * G64_STRIDE, tid, (it + 2) * BK,
                         rowBase, colBase, A, lda, B, ldb);
        cp_commit();
    }
    cp_wait<0>();

#pragma unroll
    for (int mf = 0; mf < 2; mf++) {
        int row0 = rowBase + warpM * 32 + mf * 16 + (lane >> 2);
#pragma unroll
        for (int nf = 0; nf < 4; nf++) {
            int col = colBase + warpN * 32 + nf * 8 + (lane & 3) * 2;
            if (EPI == 0) {
                float2 v0 = {alpha * acc[mf][nf][0], alpha * acc[mf][nf][1]};
                float2 v1 = {alpha * acc[mf][nf][2], alpha * acc[mf][nf][3]};
                *(float2*)(C + (size_t)row0 * ldc + col) = v0;
                *(float2*)(C + (size_t)(row0 + 8) * ldc + col) = v1;
            } else {
                *(uint32_t*)(Ch + (size_t)row0 * ldc + col) =
                    pack2h(acc[mf][nf][0], acc[mf][nf][1]);
                *(uint32_t*)(Ch + (size_t)(row0 + 8) * ldc + col) =
                    pack2h(acc[mf][nf][2], acc[mf][nf][3]);
            }
        }
    }
}

// =========== BM=128 single-product GEMM (scores): fp16 out, 3-stage pipeline ========
#define S1_A 0
#define S1_B 16384
#define S1_STRIDE 32768
#define S1_STAGES 3
#define SMEM1_BYTES (S1_STAGES*S1_STRIDE)   // 98304

__device__ __forceinline__ void load_stage1(
    uint32_t st, int tid, int k0, int rowBase, int colBase,
    const h16* A, int lda, const h16* B, int ldb)
{
#pragma unroll
    for (int i = 0; i < 4; i++) {
        int idx = tid + i * 256;
        int r = idx >> 3, ch = idx & 7;
        uint32_t so = SWZ((uint32_t)(r * 128 + ch * 16));
        cp16(st + S1_A + so, A + (size_t)(rowBase + r) * lda + k0 + ch * 8);
        cp16(st + S1_B + so, B + (size_t)(colBase + r) * ldb + k0 + ch * 8);
    }
}

__device__ void hmma_gemm128_h16out(const h16* __restrict__ A, int lda,
                                    const h16* __restrict__ B, int ldb,
                                    h16* __restrict__ Ch, int ldc, int K, float alpha,
                                    int rowBlk, int colBlk)
{
    const uint32_t sb = smem_u32(dynsmem);
    const int tid = threadIdx.x;
    const int lane = tid & 31, wid = tid >> 5;
    const int warpM = wid >> 2, warpN = wid & 3;
    const int rowBase = rowBlk * 128, colBase = colBlk * 128;

    float acc[4][4][4];
#pragma unroll
    for (int mf = 0; mf < 4; mf++)
#pragma unroll
        for (int nf = 0; nf < 4; nf++)
#pragma unroll
            for (int c = 0; c < 4; c++) acc[mf][nf][c] = 0.f;

    const int KI = K / BK;     // = 4 for scores
#pragma unroll
    for (int s = 0; s < S1_STAGES; s++) {
        if (s < KI) load_stage1(sb + s * S1_STRIDE, tid, s * BK, rowBase, colBase, A, lda, B, ldb);
        cp_commit();
    }

    int stage = 0;
    for (int it = 0; it < KI; it++) {
        cp_wait<S1_STAGES - 1>();
        __syncthreads();
        const uint32_t st = sb + stage * S1_STRIDE;
#pragma unroll
        for (int ks = 0; ks < 4; ks++) {
            uint32_t ah[4][4], bf[4][2];
            const int kk = ks * 16 + (lane >> 4) * 8;
#pragma unroll
            for (int mf = 0; mf < 4; mf++) {
                int row = warpM * 64 + mf * 16 + (lane & 15);
                ldsm4(ah[mf], st + S1_A + SWZ((uint32_t)(row * 128 + kk * 2)));
            }
#pragma unroll
            for (int nb = 0; nb < 2; nb++) {
                int nrow = warpN * 32 + nb * 16 + (lane & 15);
                uint32_t t[4];
                ldsm4(t, st + S1_B + SWZ((uint32_t)(nrow * 128 + kk * 2)));
                bf[nb*2][0] = t[0]; bf[nb*2][1] = t[2];
                bf[nb*2+1][0] = t[1]; bf[nb*2+1][1] = t[3];
            }
#pragma unroll
            for (int mf = 0; mf < 4; mf++)
#pragma unroll
                for (int nf = 0; nf < 4; nf++) mma16816(acc[mf][nf], ah[mf], bf[nf]);
        }
        __syncthreads();
        if (it + S1_STAGES < KI)
            load_stage1(sb + stage * S1_STRIDE, tid, (it + S1_STAGES) * BK,
                        rowBase, colBase, A, lda, B, ldb);
        cp_commit();
        stage = (stage + 1 == S1_STAGES) ? 0 : stage + 1;
    }
    cp_wait<0>();

#pragma unroll
    for (int mf = 0; mf < 4; mf++) {
        int row0 = rowBase + warpM * 64 + mf * 16 + (lane >> 2);
#pragma unroll
        for (int nf = 0; nf < 4; nf++) {
            int col = colBase + warpN * 32 + nf * 8 + (lane & 3) * 2;
            *(uint32_t*)(Ch + (size_t)row0 * ldc + col) =
                pack2h(alpha * acc[mf][nf][0], alpha * acc[mf][nf][1]);
            *(uint32_t*)(Ch + (size_t)(row0 + 8) * ldc + col) =
                pack2h(alpha * acc[mf][nf][2], alpha * acc[mf][nf][3]);
        }
    }
}

// ---------------- GEMM wrappers ----------------
__global__ __launch_bounds__(256) void k_gemm_f32out64(
    const h16* A, int lda, const h16* B, int ldb, float* C, int ldc, int K, float alpha)
{
    hmma_gemm64<0>(A, lda, B, ldb, C, nullptr, ldc, K, alpha, blockIdx.y, blockIdx.x);
}

// scores grid: 256 tiles/head. t in [0,120): upper-tri fp32 ZERO tiles (the required
// attn_weights zeros). t in [120,256): work tiles computing fp16 raw scores into Ph.
__global__ __launch_bounds__(256, 2) void k_gemm_scores(
    const h16* qh, const h16* kh, float* W, h16* Ph)
{
    const int bh = blockIdx.z, b = bh / NHEAD, h = bh % NHEAD;
    const int t = blockIdx.x;

    if (t < 120) {
        float* W0 = W + (size_t)bh * SEQ * SEQ;
        int a = (int)((sqrtf(8.0f * t + 1.0f) + 1.0f) * 0.5f);
        while (a * (a - 1) / 2 > t) a--;
        while ((a + 1) * a / 2 <= t) a++;
        const int tx = a, ty = t - a * (a - 1) / 2;   // tx > ty
        const int rowBase = ty * 128, colBase = tx * 128;
        const float4 z = {0.f, 0.f, 0.f, 0.f};
        const int tid = threadIdx.x;
#pragma unroll
        for (int i = 0; i < 16; i++) {
            int lin = tid + i * 256;
            int r = lin >> 5, c = (lin & 31) * 4;
            *(float4*)(W0 + (size_t)(rowBase + r) * SEQ + colBase + c) = z;
        }
        return;
    }

    const int tw = t - 120;
    int ty = (int)((sqrtf(8.0f * tw + 1.0f) - 1.0f) * 0.5f);
    while ((ty + 1) * (ty + 2) / 2 <= tw) ty++;
    while (ty * (ty + 1) / 2 > tw) ty--;
    const int tx = tw - ty * (ty + 1) / 2;

    size_t qa = (size_t)b * SEQ * DMODEL + (size_t)h * HD;
    size_t ka = (size_t)b * SEQ * HD;
    hmma_gemm128_h16out(qh + qa, DMODEL, kh + ka, HD,
                        Ph + (size_t)bh * SEQ * SEQ, SEQ, HD, 0.0625f, ty, tx);
}

// PV: BM=64 rows, LPT order (largest-K first), 64-granular causal clamp
__global__ __launch_bounds__(256) void k_gemm_pv(
    const h16* ph, const h16* vt, h16* ah_out)
{
    const int bh = blockIdx.z, b = bh / NHEAD, h = bh % NHEAD;
    const int yy = gridDim.y - 1 - blockIdx.y;
    size_t pa = (size_t)bh * SEQ * SEQ;
    size_t va = (size_t)b * HD * SEQ;
    int kmax = (yy + 1) * 64;
    size_t co = (size_t)b * SEQ * DMODEL + (size_t)h * HD;
    hmma_gemm64<1>(ph + pa, SEQ, vt + va, SEQ, nullptr, ah_out + co, DMODEL, kmax, 1.0f,
                   yy, blockIdx.x);
}

// ---------------- fused fp32 -> fp16 rounding over all 5 segments ----------------
#define CVT_N0 (ROWS*DMODEL/4)
#define CVT_N1 (DMODEL*DMODEL/4)
#define CVT_N2 (DMODEL*DMODEL/4)
#define CVT_N3 (HD*DMODEL/4)
#define CVT_N4 (HD*DMODEL/4)
#define CVT_TOTAL (CVT_N0+CVT_N1+CVT_N2+CVT_N3+CVT_N4)

__global__ __launch_bounds__(256) void k_cvt_all(
    const float4* __restrict__ X, const float4* __restrict__ Wq,
    const float4* __restrict__ Wo, const float4* __restrict__ Wk,
    const float4* __restrict__ Wv,
    uint2* __restrict__ xh, uint2* __restrict__ wqkv, uint2* __restrict__ wo)
{
    int i = blockIdx.x * 256 + threadIdx.x;
    if (i >= CVT_TOTAL) return;
    const float4* src;
    uint2* dst;
    int j = i;
    if (j < CVT_N0) { src = X; dst = xh; }
    else if ((j -= CVT_N0) < CVT_N1) { src = Wq; dst = wqkv; }
    else if ((j -= CVT_N1) < CVT_N2) { src = Wo; dst = wo; }
    else if ((j -= CVT_N2) < CVT_N3) { src = Wk; dst = wqkv + (size_t)DMODEL * DMODEL / 4; }
    else { j -= CVT_N3; src = Wv; dst = wqkv + (size_t)(DMODEL + HD) * DMODEL / 4; }
    float4 v = src[j];
    uint2 O;
    O.x = pack2h(v.x, v.y);
    O.y = pack2h(v.z, v.w);
    dst[j] = O;
}

// ---------------- fused RoPE + V-transpose (Q/K single fp16) ----------------
#define VT_BLOCKS ((SEQ/32)*(HD/32)*BATCH)           // 1024
#define ROPE_TOTAL (ROWS*(NHEAD+1)*128)
#define ROPE_BLOCKS ((ROPE_TOTAL+255)/256)

__global__ __launch_bounds__(256) void k_rope_vt(const int* __restrict__ pos) {
    const int bid = blockIdx.x;
    const int tid = threadIdx.x;
    if (bid < VT_BLOCKS) {
        __shared__ float t[32][33];
        int b = bid >> 9;
        int rem = bid & 511;
        int kblk = rem & 63;
        int nblk = rem >> 6;
        int k0 = kblk * 32, n0 = nblk * 32;
        int tx = tid & 31, ty = tid >> 5;
#pragma unroll
        for (int i = 0; i < 32; i += 8)
            t[ty + i][tx] = g_qkv[((size_t)(b * SEQ + k0 + ty + i)) * NQKV + DMODEL + HD + n0 + tx];
        __syncthreads();
#pragma unroll
        for (int i = 0; i < 32; i += 8) {
            float v = t[tx][ty + i];
            size_t o = ((size_t)(b * HD + n0 + ty + i)) * SEQ + k0 + tx;
            s_vt[o] = __float2half_rn(v);
        }
        return;
    }
    int idx = (bid - VT_BLOCKS) * 256 + tid;
    if (idx >= ROPE_TOTAL) return;
    int j = idx & 127;
    int rest = idx >> 7;
    int slot = rest % (NHEAD + 1);
    int row = rest / (NHEAD + 1);
    float p = (float)pos[row];
    float f = exp2f(-((float)(2 * j) * (1.0f / (float)HD)) * 13.287712379549449f);
    float sv, cv;
    sincosf(p * f, &sv, &cv);
    size_t src = (slot < NHEAD) ? ((size_t)row * NQKV + slot * HD + j)
                                : ((size_t)row * NQKV + DMODEL + j);
    float x1 = g_qkv[src], x2 = g_qkv[src + 128];
    float y1 = x1 * cv - x2 * sv;
    float y2 = x2 * cv + x1 * sv;
    if (slot < NHEAD) {
        size_t o = (size_t)row * DMODEL + slot * HD + j;
        s_qh[o] = __float2half_rn(y1);
        s_qh[o + 128] = __float2half_rn(y2);
    } else {
        size_t o = (size_t)row * HD + j;
        s_kh[o] = __float2half_rn(y1);
        s_kh[o + 128] = __float2half_rn(y2);
    }
}

// ---------------- softmax v5: fp16 scores in, fp32 weights + fp16 P out -------------
__global__ __launch_bounds__(256) void k_softmax(float* __restrict__ w) {
    const int row = blockIdx.x;               // bh*SEQ + q
    const int q = row & (SEQ - 1);
    const int tid = threadIdx.x;
    float4* p4 = (float4*)(w + (size_t)row * SEQ);
    uint2* ph2 = (uint2*)(s_ph + (size_t)row * SEQ);

    const float NEG = -3.4e38f;
    const int c0 = tid * 4, c1 = (tid + 256) * 4;
    uint2 r0 = (c0 <= q) ? ph2[tid]       : make_uint2(0u, 0u);
    uint2 r1 = (c1 <= q) ? ph2[tid + 256] : make_uint2(0u, 0u);
    float x[8];
    {
        float2 f;
        f = __half22float2(*(__half2*)&r0.x); x[0] = f.x; x[1] = f.y;
        f = __half22float2(*(__half2*)&r0.y); x[2] = f.x; x[3] = f.y;
        f = __half22float2(*(__half2*)&r1.x); x[4] = f.x; x[5] = f.y;
        f = __half22float2(*(__half2*)&r1.y); x[6] = f.x; x[7] = f.y;
    }
#pragma unroll
    for (int j = 0; j < 4; j++) if (c0 + j > q) x[j] = NEG;
#pragma unroll
    for (int j = 0; j < 4; j++) if (c1 + j > q) x[4 + j] = NEG;

    float m = NEG;
#pragma unroll
    for (int j = 0; j < 8; j++) m = fmaxf(m, x[j]);
#pragma unroll
    for (int o = 16; o > 0; o >>= 1) m = fmaxf(m, __shfl_xor_sync(0xFFFFFFFFu, m, o));

    __shared__ float red[8];
    __shared__ float bc[2];
    if ((tid & 31) == 0) red[tid >> 5] = m;
    __syncthreads();
    if (tid < 32) {
        float t = (tid < 8) ? red[tid] : NEG;
#pragma unroll
        for (int o = 4; o > 0; o >>= 1) t = fmaxf(t, __shfl_xor_sync(0xFFFFFFFFu, t, o));
        if (tid == 0) bc[0] = t;
    }
    __syncthreads();
    m = bc[0];

    float e[8];
    float s = 0.f;
#pragma unroll
    for (int j = 0; j < 8; j++) {
        e[j] = (x[j] > -1e37f) ? expf(x[j] - m) : 0.f;
        s += e[j];
    }
#pragma unroll
    for (int o = 16; o > 0; o >>= 1) s += __shfl_xor_sync(0xFFFFFFFFu, s, o);
    if ((tid & 31) == 0) red[tid >> 5] = s;
    __syncthreads();
    if (tid < 32) {
        float t = (tid < 8) ? red[tid] : 0.f;
#pragma unroll
        for (int o = 4; o > 0; o >>= 1) t += __shfl_xor_sync(0xFFFFFFFFu, t, o);
        if (tid == 0) bc[1] = t;
    }
    __syncthreads();
    const float inv = 1.0f / bc[1];

#pragma unroll
    for (int j = 0; j < 8; j++) e[j] *= inv;
    const int kmax128 = ((q >> 7) + 1) << 7;   // fp32 zeros beyond: written by zero tiles
    const int kmax64  = ((q >> 6) + 1) << 6;   // PV never reads P beyond this
    float4 o0 = {e[0], e[1], e[2], e[3]};
    float4 o1 = {e[4], e[5], e[6], e[7]};
    if (c0 < kmax128) p4[tid] = o0;
    if (c1 < kmax128) p4[tid + 256] = o1;
    uint2 h0 = {pack2h(e[0], e[1]), pack2h(e[2], e[3])};
    uint2 h1 = {pack2h(e[4], e[5]), pack2h(e[6], e[7])};
    if (c0 < kmax64) ph2[tid] = h0;
    if (c1 < kmax64) ph2[tid + 256] = h1;
}

// ---------------- launch ----------------
static void* sym(const void* s) { void* p = nullptr; cudaGetSymbolAddress(&p, s); return p; }

extern "C" void kernel_launch(void* const* d_in, const int* in_sizes, int n_in,
                              void* d_out, int out_size) {
    const float* hidden = (const float*)d_in[0];
    const int*   pos    = (const int*)d_in[2];
    const float* Wq     = (const float*)d_in[3];
    const float* Wk     = (const float*)d_in[4];
    const float* Wv     = (const float*)d_in[5];
    const float* Wo     = (const float*)d_in[6];

    float* out      = (float*)d_out;
    float* weights  = out + (size_t)ROWS * DMODEL;   // (B, H, S, S)

    cudaFuncSetAttribute(k_gemm_f32out64, cudaFuncAttributeMaxDynamicSharedMemorySize, SMEM64_BYTES);
    cudaFuncSetAttribute(k_gemm_pv,       cudaFuncAttributeMaxDynamicSharedMemorySize, SMEM64_BYTES);
    cudaFuncSetAttribute(k_gemm_scores,   cudaFuncAttributeMaxDynamicSharedMemorySize, SMEM1_BYTES);

    h16 *xh = (h16*)sym(s_xh), *wqkv = (h16*)sym(s_wqkv), *wo = (h16*)sym(s_wo);
    h16 *qh = (h16*)sym(s_qh), *kh = (h16*)sym(s_kh), *vt = (h16*)sym(s_vt);
    h16 *ph = (h16*)sym(s_ph), *ah = (h16*)sym(s_ah);
    float *gqkv = (float*)sym(g_qkv);

    // 1. one fused rounding pass over X, Wq, Wo, Wk, Wv
    k_cvt_all<<<(CVT_TOTAL + 255) / 256, 256>>>(
        (const float4*)hidden, (const float4*)Wq, (const float4*)Wo,
        (const float4*)Wk, (const float4*)Wv,
        (uint2*)xh, (uint2*)wqkv, (uint2*)wo);

    // 2. fused QKV projection (BM=64 tiles: 1280 CTAs)
    k_gemm_f32out64<<<dim3(NQKV / 128, ROWS / 64), 256, SMEM64_BYTES>>>(
        xh, DMODEL, wqkv, DMODEL, gqkv, NQKV, DMODEL, 1.0f);

    // 3. fused RoPE + V transpose (Q, K single fp16)
    k_rope_vt<<<VT_BLOCKS + ROPE_BLOCKS, 256>>>(pos);

    // 4. scores: 120 fp32 zero tiles + 136 work tiles writing fp16 scores to s_ph
    k_gemm_scores<<<dim3(256, 1, BH), 256, SMEM1_BYTES>>>(qh, kh, weights, ph);

    // 5. softmax v5: fp16 in, fp32 weights (bounded) + fp16 P (in place) out
    k_softmax<<<BH * SEQ, 256>>>(weights);

    // 6. P @ V (BM=64, 64-granular causal clamp, LPT) -> fp16 attn
    k_gemm_pv<<<dim3(HD / 128, SEQ / 64, BH), 256, SMEM64_BYTES>>>(ph, vt, ah);

    // 7. output projection (BM=64 tiles: 1024 CTAs)
    k_gemm_f32out64<<<dim3(DMODEL / 128, ROWS / 64), 256, SMEM64_BYTES>>>(
        ah, DMODEL, wo, DMODEL, out, DMODEL, DMODEL, 1.0f);
}